// round 9
// baseline (speedup 1.0000x reference)
#include <cuda_runtime.h>
#include <cstdint>

// CondConv2d via fp16 mma.sync.m16n8k8 implicit GEMM (f32 accumulate).
// R9: 4 chunks x 8ci, software-pipelined: convert(next) + stage(next2)
// overlap compute(cur); one barrier per chunk.
// CTA = 8h x 64w x 32co of one batch; 256 threads / 8 warps;
// warp = 2h x 32px x 32co.

#define B_    16
#define CIN_  32
#define HW_   256
#define COUT_ 32
#define NEXP  8
#define NPARAM 9216

// ---- smem layout in 4-byte units ----
#define RAWP   72                 // raw f32 pitch; raw col rc <-> iw = w0 + rc - 4
#define SCR_SZ 5760               // 8 planes x 10 rows x 72
#define SCR0_U 0
#define SCR1_U 5760
#define XPH    76                 // packed pitch; 760 % 32 == 24 -> banks distinct
#define XSH_SZ 3040               // 4 jpairs x 10 rows x 76 ; col c <-> rc c
#define XSH0_U 11520
#define XSH1_U 14560
#define WS_U   17600              // all 4 chunks: 4 x 1152 words
#define BIAS_U 22208
#define SMEM_U 22240
#define SMEM_BYTES (SMEM_U * 4)   // 88960 B -> 2 CTA/SM

__device__ uint32_t g_wt_h[B_ * 4608];  // [b][cc][t][lane][w] f16x2 words
__device__ float    g_bias[B_ * COUT_];

__device__ __forceinline__ uint32_t smem_u32(const void* p) {
    uint32_t a;
    asm("{ .reg .u64 t; cvta.to.shared.u64 t, %1; cvt.u32.u64 %0, t; }" : "=r"(a) : "l"(p));
    return a;
}
__device__ __forceinline__ uint32_t pack_f16x2(float hi, float lo) {
    uint32_t d;
    asm("cvt.rn.f16x2.f32 %0, %1, %2;" : "=r"(d) : "f"(hi), "f"(lo));
    return d;
}
__device__ __forceinline__ void mma_f16_k8(float c[4], uint32_t a0, uint32_t a1,
                                           uint32_t b0) {
    asm volatile(
        "mma.sync.aligned.m16n8k8.row.col.f32.f16.f16.f32 "
        "{%0,%1,%2,%3}, {%4,%5}, {%6}, {%0,%1,%2,%3};"
        : "+f"(c[0]), "+f"(c[1]), "+f"(c[2]), "+f"(c[3])
        : "r"(a0), "r"(a1), "r"(b0));
}
__device__ __forceinline__ void cp_async4(uint32_t dst, const void* src, uint32_t sz) {
    asm volatile("cp.async.ca.shared.global [%0], [%1], 4, %2;"
                 :: "r"(dst), "l"(src), "r"(sz) : "memory");
}
__device__ __forceinline__ void cp_async16(uint32_t dst, const void* src) {
    asm volatile("cp.async.cg.shared.global [%0], [%1], 16;"
                 :: "r"(dst), "l"(src) : "memory");
}
__device__ __forceinline__ void cp_async16z(uint32_t dst, const void* src, uint32_t sz) {
    asm volatile("cp.async.cg.shared.global [%0], [%1], 16, %2;"
                 :: "r"(dst), "l"(src), "r"(sz) : "memory");
}
#define CP_COMMIT() asm volatile("cp.async.commit_group;" ::: "memory")
#define CP_WAIT0()  asm volatile("cp.async.wait_group 0;" ::: "memory")

// ---------------------------------------------------------------------------
// Kernel 1: mix experts -> fragment-ordered fp16 weights + bias.
// word index (per b): cc*1152 + t*128 + lane*4 + w
//   co = ((w&1)<<3) + ((w>>1)<<4) + g ; ci = cc*8 + 2*tig, pack {ci, ci+1}.
// ---------------------------------------------------------------------------
__global__ void condconv_prep_kernel(const float* __restrict__ rw,
                                     const float* __restrict__ ew,
                                     const float* __restrict__ eb) {
    int b = blockIdx.x, cc = blockIdx.y;
    int tid = threadIdx.x;
    float r[NEXP];
#pragma unroll
    for (int e = 0; e < NEXP; e++) r[e] = rw[b * NEXP + e];

    for (int i = tid; i < 1152; i += 256) {
        int t    = i >> 7;
        int r2   = i & 127;
        int lane = r2 >> 2;
        int w    = r2 & 3;
        int g = lane >> 2, tig = lane & 3;
        int co = ((w & 1) << 3) + ((w >> 1) << 4) + g;
        int ci = cc * 8 + 2 * tig;
        int src = co * (CIN_ * 9) + ci * 9 + t;
        float s_lo = 0.f, s_hi = 0.f;
#pragma unroll
        for (int e = 0; e < NEXP; e++) {
            s_lo += r[e] * ew[e * NPARAM + src];
            s_hi += r[e] * ew[e * NPARAM + src + 9];    // ci+1
        }
        g_wt_h[b * 4608 + cc * 1152 + i] = pack_f16x2(s_hi, s_lo);
    }
    if (cc == 0 && tid < COUT_) {
        float s = 0.f;
#pragma unroll
        for (int e = 0; e < NEXP; e++) s += r[e] * eb[e * COUT_ + tid];
        g_bias[b * COUT_ + tid] = s;
    }
}

// ---------------------------------------------------------------------------
// stage 8 x-planes of chunk q into scr (raw f32). interior rc 4..67, halo 3/68.
// ---------------------------------------------------------------------------
__device__ __forceinline__ void stage_x(uint32_t scr, const float* __restrict__ xq,
                                        int h0, int w0, int tid) {
    for (int i = tid; i < 1280; i += 256) {
        int pl  = i / 160;
        int r1  = i - pl * 160;
        int row = r1 >> 4;
        int v   = r1 & 15;
        int ih  = h0 - 1 + row;
        bool ok = (unsigned)ih < 256u;
        const float* src = xq + (size_t)pl * (HW_ * HW_) + (ok ? ih * HW_ : 0) + w0 + v * 4;
        cp_async16z(scr + (uint32_t)(pl * (10 * RAWP) + row * RAWP + 4 + v * 4) * 4,
                    src, ok ? 16u : 0u);
    }
    for (int i = tid; i < 160; i += 256) {
        int pl   = i / 20;
        int r1   = i - pl * 20;
        int row  = r1 >> 1;
        int side = r1 & 1;
        int ih = h0 - 1 + row;
        int iw = side ? (w0 + 64) : (w0 - 1);
        bool ok = ((unsigned)ih < 256u) && ((unsigned)iw < 256u);
        const float* src = xq + (size_t)pl * (HW_ * HW_) + (ok ? (ih * HW_ + iw) : 0);
        cp_async4(scr + (uint32_t)(pl * (10 * RAWP) + row * RAWP + (side ? 68 : 3)) * 4,
                  src, ok ? 4u : 0u);
    }
}

// convert scr f32 -> xsh packed f16x2 over adjacent planes; cols 0..69 (35 f2 pairs)
__device__ __forceinline__ void convert_chunk(const float* scr, uint32_t* xsh, int tid) {
    for (int i = tid; i < 1400; i += 256) {
        int j   = i / 350;
        int r1  = i - j * 350;
        int row = r1 / 35;
        int p2  = r1 - row * 35;
        const float* s0 = scr + (2 * j)     * (10 * RAWP) + row * RAWP + 2 * p2;
        const float* s1 = scr + (2 * j + 1) * (10 * RAWP) + row * RAWP + 2 * p2;
        float2 f0 = *(const float2*)s0;
        float2 f1 = *(const float2*)s1;
        uint2 o;
        o.x = pack_f16x2(f1.x, f0.x);
        o.y = pack_f16x2(f1.y, f0.y);
        *(uint2*)(xsh + j * (10 * XPH) + row * XPH + 2 * p2) = o;
    }
}

// compute one 8-ci chunk
__device__ __forceinline__ void compute_chunk(const uint32_t* xsh, const uint32_t* ws,
                                              float acc[2][2][4][4],
                                              int lane, int g, int tig, int wy, int wh) {
    const uint4* wf = (const uint4*)ws + lane;
    const uint32_t* xf = xsh + (2 * wy) * XPH + wh * 32 + g + 3 + tig * (10 * XPH);

#pragma unroll
    for (int kw = 0; kw < 3; kw++) {
        uint32_t B[4][4];
#pragma unroll
        for (int xr = 0; xr < 4; xr++) {
            const uint32_t* xt = xf + xr * XPH + kw;
#pragma unroll
            for (int nt = 0; nt < 4; nt++) B[xr][nt] = xt[nt * 8];
        }
#pragma unroll
        for (int kh = 0; kh < 3; kh++) {
            const int t = kh * 3 + kw;
            uint4 q = wf[t * 32];
#pragma unroll
            for (int r = 0; r < 2; r++) {
                const int xr = r + kh;
#pragma unroll
                for (int nt = 0; nt < 4; nt++) {
                    mma_f16_k8(acc[r][0][nt], q.x, q.y, B[xr][nt]);
                    mma_f16_k8(acc[r][1][nt], q.z, q.w, B[xr][nt]);
                }
            }
        }
    }
}

// ---------------------------------------------------------------------------
// Kernel 2: conv. Grid (4, 32, 16); 256 threads, 8 warps.
// ---------------------------------------------------------------------------
__global__ __launch_bounds__(256, 2)
void condconv_mma_kernel(const float* __restrict__ x, float* __restrict__ out) {
    extern __shared__ float sm[];
    const uint32_t sbase = smem_u32(sm);

    const int b  = blockIdx.z;
    const int h0 = blockIdx.y * 8;
    const int w0 = blockIdx.x * 64;
    const int tid = threadIdx.x;
    const int lane = tid & 31, wid = tid >> 5;
    const int g = lane >> 2, tig = lane & 3;
    const int wy = wid >> 1, wh = wid & 1;

    const uint32_t* gw = g_wt_h + b * 4608;
    const float* xb = x + (size_t)b * CIN_ * HW_ * HW_;

    if (tid < COUT_) sm[BIAS_U + tid] = g_bias[b * COUT_ + tid];

    float acc[2][2][4][4];
#pragma unroll
    for (int r = 0; r < 2; r++)
#pragma unroll
        for (int mt = 0; mt < 2; mt++)
#pragma unroll
            for (int nt = 0; nt < 4; nt++)
#pragma unroll
                for (int i = 0; i < 4; i++) acc[r][mt][nt][i] = 0.f;

    const uint32_t scr_a[2] = {sbase + SCR0_U * 4, sbase + SCR1_U * 4};
    const float*   scr_p[2] = {sm + SCR0_U, sm + SCR1_U};
    uint32_t* xsh_p[2] = {(uint32_t*)(sm + XSH0_U), (uint32_t*)(sm + XSH1_U)};
    const uint32_t* ws_all = (const uint32_t*)(sm + WS_U);

    // prologue: weights (all 4 chunks) + x chunk0 -> G0 ; x chunk1 -> G1
    for (int i = tid; i < 1152; i += 256)
        cp_async16(sbase + (WS_U + i * 4) * 4, gw + i * 4);
    stage_x(scr_a[0], xb, h0, w0, tid);
    CP_COMMIT();
    stage_x(scr_a[1], xb + (size_t)8 * HW_ * HW_, h0, w0, tid);
    CP_COMMIT();
    asm volatile("cp.async.wait_group 1;" ::: "memory");
    __syncthreads();
    convert_chunk(scr_p[0], xsh_p[0], tid);

#pragma unroll 1
    for (int cc = 0; cc < 4; cc++) {
        if (cc < 3) {
            CP_WAIT0();             // x(cc+1) staged
            __syncthreads();        // scr(cc+1) + convert(cc) visible to all
            convert_chunk(scr_p[(cc + 1) & 1], xsh_p[(cc + 1) & 1], tid);
            if (cc < 2) {
                stage_x(scr_a[cc & 1], xb + (size_t)(cc + 2) * 8 * HW_ * HW_,
                        h0, w0, tid);
                CP_COMMIT();
            }
        } else {
            __syncthreads();        // convert(3) visible
        }
        compute_chunk(xsh_p[cc & 1], ws_all + cc * 1152, acc, lane, g, tig, wy, wh);
    }

    // epilogue
    const float* bs = sm + BIAS_U;
#pragma unroll
    for (int r = 0; r < 2; r++) {
        const int oh = h0 + 2 * wy + r;
#pragma unroll
        for (int mt = 0; mt < 2; mt++) {
#pragma unroll
            for (int nt = 0; nt < 4; nt++) {
                int co = mt * 16 + g;
                int pw = w0 + wh * 32 + nt * 8 + 2 * tig;
                float2 v0, v1;
                v0.x = acc[r][mt][nt][0] + bs[co];
                v0.y = acc[r][mt][nt][1] + bs[co];
                v1.x = acc[r][mt][nt][2] + bs[co + 8];
                v1.y = acc[r][mt][nt][3] + bs[co + 8];
                *(float2*)&out[(((size_t)b * COUT_ + co)     * HW_ + oh) * HW_ + pw] = v0;
                *(float2*)&out[(((size_t)b * COUT_ + co + 8) * HW_ + oh) * HW_ + pw] = v1;
            }
        }
    }
}

// ---------------------------------------------------------------------------
extern "C" void kernel_launch(void* const* d_in, const int* in_sizes, int n_in,
                              void* d_out, int out_size) {
    const float* x  = (const float*)d_in[0];
    const float* rw = (const float*)d_in[1];
    const float* ew = (const float*)d_in[2];
    const float* eb = (const float*)d_in[3];
    float* out = (float*)d_out;

    condconv_prep_kernel<<<dim3(B_, 4), 256>>>(rw, ew, eb);

    cudaFuncSetAttribute(condconv_mma_kernel,
                         cudaFuncAttributeMaxDynamicSharedMemorySize, SMEM_BYTES);
    dim3 grid(HW_ / 64, HW_ / 8, B_);
    condconv_mma_kernel<<<grid, 256, SMEM_BYTES>>>(x, out);
}

// round 10
// speedup vs baseline: 1.2473x; 1.2473x over previous
#include <cuda_runtime.h>
#include <cstdint>

// CondConv2d via fp16 mma.sync.m16n8k16 implicit GEMM (f32 accumulate).
// R10: single-shot staging (direct LDG -> cvt -> STS.128, all 32 ci resident),
// one barrier, two back-to-back 16-ci compute halves. Reverts R9's k8 regression.
// CTA = 8h x 64w x 32co of one batch; 256 threads / 8 warps;
// warp = 2h x 32px x 32co.

#define B_    16
#define CIN_  32
#define HW_   256
#define COUT_ 32
#define NEXP  8
#define NPARAM 9216

// ---- smem layout in 4-byte units ----
// xsh: 16 ci-pairs x 10 rows x pitch 76 (col c <-> iw = w0 - 4 + c; interior
//      c 4..67, halo-left c 3, halo-right c 68). 760 % 32 == 24 -> B banks ok.
#define XPH    76
#define XSH_U  0
#define WS_U   12160              // 2 chunks x 2304 words, k16 fragment order
#define BIAS_U 16768
#define SMEM_U 16800
#define SMEM_BYTES (SMEM_U * 4)   // 67200 B -> 2 CTA/SM

__device__ uint32_t g_wt_h[B_ * 4608];   // [b][cc][t][mt][lane][w] f16x2 words
__device__ float    g_bias[B_ * COUT_];

__device__ __forceinline__ uint32_t smem_u32(const void* p) {
    uint32_t a;
    asm("{ .reg .u64 t; cvta.to.shared.u64 t, %1; cvt.u32.u64 %0, t; }" : "=r"(a) : "l"(p));
    return a;
}
__device__ __forceinline__ uint32_t pack_f16x2(float hi, float lo) {
    uint32_t d;
    asm("cvt.rn.f16x2.f32 %0, %1, %2;" : "=r"(d) : "f"(hi), "f"(lo));
    return d;
}
__device__ __forceinline__ void mma_f16(float c[4], const uint32_t a[4],
                                        uint32_t b0, uint32_t b1) {
    asm volatile(
        "mma.sync.aligned.m16n8k16.row.col.f32.f16.f16.f32 "
        "{%0,%1,%2,%3}, {%4,%5,%6,%7}, {%8,%9}, {%0,%1,%2,%3};"
        : "+f"(c[0]), "+f"(c[1]), "+f"(c[2]), "+f"(c[3])
        : "r"(a[0]), "r"(a[1]), "r"(a[2]), "r"(a[3]), "r"(b0), "r"(b1));
}
__device__ __forceinline__ void cp_async16(uint32_t dst, const void* src) {
    asm volatile("cp.async.cg.shared.global [%0], [%1], 16;"
                 :: "r"(dst), "l"(src) : "memory");
}
#define CP_COMMIT() asm volatile("cp.async.commit_group;" ::: "memory")
#define CP_WAIT0()  asm volatile("cp.async.wait_group 0;" ::: "memory")

// ---------------------------------------------------------------------------
// Kernel 1: mix experts -> fragment-ordered fp16 weights + bias (same as R8).
// word index (per b): ((cc*9 + t)*2 + mt)*128 + lane*4 + w
//   co = mt*16 + g + (w&1)*8 ; ci = cc*16 + 2*tig + (w>>1)*8, pack {ci, ci+1}.
// ---------------------------------------------------------------------------
__global__ void condconv_prep_kernel(const float* __restrict__ rw,
                                     const float* __restrict__ ew,
                                     const float* __restrict__ eb) {
    int b = blockIdx.x, cc = blockIdx.y;
    int tid = threadIdx.x;
    float r[NEXP];
#pragma unroll
    for (int e = 0; e < NEXP; e++) r[e] = rw[b * NEXP + e];

    for (int i = tid; i < 2304; i += 256) {
        int t    = i >> 8;
        int r2   = i & 255;
        int mt   = r2 >> 7;
        int lane = (r2 >> 2) & 31;
        int w    = r2 & 3;
        int g = lane >> 2, tig = lane & 3;
        int co = mt * 16 + g + (w & 1) * 8;
        int ci = cc * 16 + 2 * tig + (w >> 1) * 8;
        int src = co * (CIN_ * 9) + ci * 9 + t;
        float s_lo = 0.f, s_hi = 0.f;
#pragma unroll
        for (int e = 0; e < NEXP; e++) {
            s_lo += r[e] * ew[e * NPARAM + src];
            s_hi += r[e] * ew[e * NPARAM + src + 9];   // ci+1
        }
        g_wt_h[(b * 2 + cc) * 2304 + i] = pack_f16x2(s_hi, s_lo);
    }
    if (cc == 0 && tid < COUT_) {
        float s = 0.f;
#pragma unroll
        for (int e = 0; e < NEXP; e++) s += r[e] * eb[e * COUT_ + tid];
        g_bias[b * COUT_ + tid] = s;
    }
}

// ---------------------------------------------------------------------------
// compute one 16-ci half from the resident xsh buffer
// ---------------------------------------------------------------------------
__device__ __forceinline__ void compute_half(const uint32_t* xsh, const uint32_t* ws,
                                             float acc[2][2][4][4],
                                             int lane, int g, int tig, int wy, int wh) {
    const uint4* wf = (const uint4*)ws + lane;
    const uint32_t* xf = xsh + (2 * wy) * XPH + wh * 32 + g + 3 + tig * (10 * XPH);

#pragma unroll
    for (int kw = 0; kw < 3; kw++) {
        uint32_t B0[4][4], B1[4][4];
#pragma unroll
        for (int xr = 0; xr < 4; xr++) {
            const uint32_t* xt = xf + xr * XPH + kw;
#pragma unroll
            for (int nt = 0; nt < 4; nt++) {
                B0[xr][nt] = xt[nt * 8];
                B1[xr][nt] = xt[nt * 8 + 4 * (10 * XPH)];
            }
        }
#pragma unroll
        for (int kh = 0; kh < 3; kh++) {
            const int t = kh * 3 + kw;
            uint4 q0 = wf[(t * 2) * 32];
            uint4 q1 = wf[(t * 2 + 1) * 32];
            uint32_t a0[4] = {q0.x, q0.y, q0.z, q0.w};
            uint32_t a1[4] = {q1.x, q1.y, q1.z, q1.w};
#pragma unroll
            for (int r = 0; r < 2; r++) {
                const int xr = r + kh;
#pragma unroll
                for (int nt = 0; nt < 4; nt++) {
                    mma_f16(acc[r][0][nt], a0, B0[xr][nt], B1[xr][nt]);
                    mma_f16(acc[r][1][nt], a1, B0[xr][nt], B1[xr][nt]);
                }
            }
        }
    }
}

// ---------------------------------------------------------------------------
// Kernel 2: conv. Grid (4, 32, 16); 256 threads, 8 warps.
// ---------------------------------------------------------------------------
__global__ __launch_bounds__(256, 2)
void condconv_mma_kernel(const float* __restrict__ x, float* __restrict__ out) {
    extern __shared__ float sm[];
    const uint32_t sbase = smem_u32(sm);

    const int b  = blockIdx.z;
    const int h0 = blockIdx.y * 8;
    const int w0 = blockIdx.x * 64;
    const int tid = threadIdx.x;
    const int lane = tid & 31, wid = tid >> 5;
    const int g = lane >> 2, tig = lane & 3;
    const int wy = wid >> 1, wh = wid & 1;

    const uint32_t* gw = g_wt_h + b * 4608;
    const float* xb = x + (size_t)b * CIN_ * HW_ * HW_;
    uint32_t* xsh = (uint32_t*)(sm + XSH_U);

    // ---- prefetch weights (both halves) via cp.async ----
    for (int i = tid; i < 1152; i += 256)
        cp_async16(sbase + (WS_U + i * 4) * 4, gw + i * 4);
    CP_COMMIT();

    if (tid < COUT_) sm[BIAS_U + tid] = g_bias[b * COUT_ + tid];

    // ---- stage all 32 ci: LDG.128 pairs -> f16x2 -> STS.128 ----
    // interior: 16 jpairs x 10 rows x 16 vec4 (iw = w0 + 4v -> col 4+4v)
    for (int i = tid; i < 2560; i += 256) {
        int v    = i & 15;
        int rest = i >> 4;
        int j    = rest / 10;
        int row  = rest - j * 10;
        int ih   = h0 - 1 + row;
        float4 f0, f1;
        if ((unsigned)ih < 256u) {
            const float* p0 = xb + (size_t)(2 * j) * (HW_ * HW_) + ih * HW_ + w0 + 4 * v;
            f0 = *(const float4*)p0;
            f1 = *(const float4*)(p0 + HW_ * HW_);
        } else {
            f0 = make_float4(0.f, 0.f, 0.f, 0.f);
            f1 = f0;
        }
        uint4 o;
        o.x = pack_f16x2(f1.x, f0.x);
        o.y = pack_f16x2(f1.y, f0.y);
        o.z = pack_f16x2(f1.z, f0.z);
        o.w = pack_f16x2(f1.w, f0.w);
        *(uint4*)(xsh + j * (10 * XPH) + row * XPH + 4 + 4 * v) = o;
    }
    // halo: 16 jpairs x 10 rows x 2 sides (iw w0-1 -> col 3, w0+64 -> col 68)
    for (int i = tid; i < 320; i += 256) {
        int side = i & 1;
        int rest = i >> 1;
        int j    = rest / 10;
        int row  = rest - j * 10;
        int ih = h0 - 1 + row;
        int iw = side ? (w0 + 64) : (w0 - 1);
        float f0 = 0.f, f1 = 0.f;
        if (((unsigned)ih < 256u) && ((unsigned)iw < 256u)) {
            const float* p0 = xb + (size_t)(2 * j) * (HW_ * HW_) + ih * HW_ + iw;
            f0 = p0[0];
            f1 = p0[HW_ * HW_];
        }
        xsh[j * (10 * XPH) + row * XPH + (side ? 68 : 3)] = pack_f16x2(f1, f0);
    }

    float acc[2][2][4][4];
#pragma unroll
    for (int r = 0; r < 2; r++)
#pragma unroll
        for (int mt = 0; mt < 2; mt++)
#pragma unroll
            for (int nt = 0; nt < 4; nt++)
#pragma unroll
                for (int i = 0; i < 4; i++) acc[r][mt][nt][i] = 0.f;

    CP_WAIT0();
    __syncthreads();   // the only barrier

    const uint32_t* ws = (const uint32_t*)(sm + WS_U);
    compute_half(xsh,                 ws,        acc, lane, g, tig, wy, wh);
    compute_half(xsh + 8 * (10 * XPH), ws + 2304, acc, lane, g, tig, wy, wh);

    // ---- epilogue ----
    const float* bs = sm + BIAS_U;
#pragma unroll
    for (int r = 0; r < 2; r++) {
        const int oh = h0 + 2 * wy + r;
#pragma unroll
        for (int mt = 0; mt < 2; mt++) {
#pragma unroll
            for (int nt = 0; nt < 4; nt++) {
                int co = mt * 16 + g;
                int pw = w0 + wh * 32 + nt * 8 + 2 * tig;
                float2 v0, v1;
                v0.x = acc[r][mt][nt][0] + bs[co];
                v0.y = acc[r][mt][nt][1] + bs[co];
                v1.x = acc[r][mt][nt][2] + bs[co + 8];
                v1.y = acc[r][mt][nt][3] + bs[co + 8];
                *(float2*)&out[(((size_t)b * COUT_ + co)     * HW_ + oh) * HW_ + pw] = v0;
                *(float2*)&out[(((size_t)b * COUT_ + co + 8) * HW_ + oh) * HW_ + pw] = v1;
            }
        }
    }
}

// ---------------------------------------------------------------------------
extern "C" void kernel_launch(void* const* d_in, const int* in_sizes, int n_in,
                              void* d_out, int out_size) {
    const float* x  = (const float*)d_in[0];
    const float* rw = (const float*)d_in[1];
    const float* ew = (const float*)d_in[2];
    const float* eb = (const float*)d_in[3];
    float* out = (float*)d_out;

    condconv_prep_kernel<<<dim3(B_, 2), 256>>>(rw, ew, eb);

    cudaFuncSetAttribute(condconv_mma_kernel,
                         cudaFuncAttributeMaxDynamicSharedMemorySize, SMEM_BYTES);
    dim3 grid(HW_ / 64, HW_ / 8, B_);
    condconv_mma_kernel<<<grid, 256, SMEM_BYTES>>>(x, out);
}

// round 11
// speedup vs baseline: 1.4414x; 1.1556x over previous
#include <cuda_runtime.h>
#include <cstdint>

// CondConv2d via fp16 mma.sync.m16n8k16 implicit GEMM (f32 accumulate).
// R11: each CTA processes 2 h-tiles (4 jobs of 16-ci halves) with cross-job
// cp.async prefetch: stage(j+1) always overlaps compute(j). Weights loaded
// once per CTA. Single xsh buffer; scr reused per job.
// CTA job = 8h x 64w x 32co x 16ci; 256 threads / 8 warps; warp = 2h x 32px x 32co.

#define B_    16
#define CIN_  32
#define HW_   256
#define COUT_ 32
#define NEXP  8
#define NPARAM 9216

// ---- smem layout in 4-byte units ----
#define RAWP   72                 // raw f32 pitch; raw col rc <-> iw = w0 - 4 + rc
#define SCR_U  0                  // 16 planes x 10 rows x 72 = 11520 words
#define XPH    76                 // 760 % 32 == 24 -> B-frag banks distinct
#define XSH_U  11520              // 8 jpairs x 10 rows x 76 = 6080 words
#define WS_U   17600              // 2 halves x 2304 words (k16 fragment order)
#define BIAS_U 22208
#define SMEM_U 22240
#define SMEM_BYTES (SMEM_U * 4)   // 88960 B -> 2 CTA/SM

__device__ uint32_t g_wt_h[B_ * 4608];   // [b][cc][t][mt][lane][w] f16x2 words
__device__ float    g_bias[B_ * COUT_];

__device__ __forceinline__ uint32_t smem_u32(const void* p) {
    uint32_t a;
    asm("{ .reg .u64 t; cvta.to.shared.u64 t, %1; cvt.u32.u64 %0, t; }" : "=r"(a) : "l"(p));
    return a;
}
__device__ __forceinline__ uint32_t pack_f16x2(float hi, float lo) {
    uint32_t d;
    asm("cvt.rn.f16x2.f32 %0, %1, %2;" : "=r"(d) : "f"(hi), "f"(lo));
    return d;
}
__device__ __forceinline__ void mma_f16(float c[4], const uint32_t a[4],
                                        uint32_t b0, uint32_t b1) {
    asm volatile(
        "mma.sync.aligned.m16n8k16.row.col.f32.f16.f16.f32 "
        "{%0,%1,%2,%3}, {%4,%5,%6,%7}, {%8,%9}, {%0,%1,%2,%3};"
        : "+f"(c[0]), "+f"(c[1]), "+f"(c[2]), "+f"(c[3])
        : "r"(a[0]), "r"(a[1]), "r"(a[2]), "r"(a[3]), "r"(b0), "r"(b1));
}
__device__ __forceinline__ void cp_async4(uint32_t dst, const void* src, uint32_t sz) {
    asm volatile("cp.async.ca.shared.global [%0], [%1], 4, %2;"
                 :: "r"(dst), "l"(src), "r"(sz) : "memory");
}
__device__ __forceinline__ void cp_async16(uint32_t dst, const void* src) {
    asm volatile("cp.async.cg.shared.global [%0], [%1], 16;"
                 :: "r"(dst), "l"(src) : "memory");
}
__device__ __forceinline__ void cp_async16z(uint32_t dst, const void* src, uint32_t sz) {
    asm volatile("cp.async.cg.shared.global [%0], [%1], 16, %2;"
                 :: "r"(dst), "l"(src), "r"(sz) : "memory");
}
#define CP_COMMIT() asm volatile("cp.async.commit_group;" ::: "memory")
#define CP_WAIT0()  asm volatile("cp.async.wait_group 0;" ::: "memory")

// ---------------------------------------------------------------------------
// Kernel 1: mix experts -> fragment-ordered fp16 weights + bias (k16 order).
// word index (per b): ((cc*9 + t)*2 + mt)*128 + lane*4 + w
//   co = mt*16 + g + (w&1)*8 ; ci = cc*16 + 2*tig + (w>>1)*8, pack {ci, ci+1}.
// ---------------------------------------------------------------------------
__global__ void condconv_prep_kernel(const float* __restrict__ rw,
                                     const float* __restrict__ ew,
                                     const float* __restrict__ eb) {
    int b = blockIdx.x, cc = blockIdx.y;
    int tid = threadIdx.x;
    float r[NEXP];
#pragma unroll
    for (int e = 0; e < NEXP; e++) r[e] = rw[b * NEXP + e];

    for (int i = tid; i < 2304; i += 256) {
        int t    = i >> 8;
        int r2   = i & 255;
        int mt   = r2 >> 7;
        int lane = (r2 >> 2) & 31;
        int w    = r2 & 3;
        int g = lane >> 2, tig = lane & 3;
        int co = mt * 16 + g + (w & 1) * 8;
        int ci = cc * 16 + 2 * tig + (w >> 1) * 8;
        int src = co * (CIN_ * 9) + ci * 9 + t;
        float s_lo = 0.f, s_hi = 0.f;
#pragma unroll
        for (int e = 0; e < NEXP; e++) {
            s_lo += r[e] * ew[e * NPARAM + src];
            s_hi += r[e] * ew[e * NPARAM + src + 9];   // ci+1
        }
        g_wt_h[(b * 2 + cc) * 2304 + i] = pack_f16x2(s_hi, s_lo);
    }
    if (cc == 0 && tid < COUT_) {
        float s = 0.f;
#pragma unroll
        for (int e = 0; e < NEXP; e++) s += r[e] * eb[e * COUT_ + tid];
        g_bias[b * COUT_ + tid] = s;
    }
}

// ---------------------------------------------------------------------------
// stage 16 planes (one ci-half) of one tile into scr as raw f32 via cp.async.
// xq points to the first plane of this half.
// ---------------------------------------------------------------------------
__device__ __forceinline__ void stage_raw(uint32_t scr, const float* __restrict__ xq,
                                          int h0, int w0, int tid) {
    for (int i = tid; i < 2560; i += 256) {            // interior 16B
        int v    = i & 15;
        int rest = i >> 4;
        int pl   = rest / 10;
        int row  = rest - pl * 10;
        int ih   = h0 - 1 + row;
        bool ok = (unsigned)ih < 256u;
        const float* src = xq + (size_t)pl * (HW_ * HW_) + (ok ? ih * HW_ : 0) + w0 + 4 * v;
        cp_async16z(scr + (uint32_t)(pl * (10 * RAWP) + row * RAWP + 4 + 4 * v) * 4,
                    src, ok ? 16u : 0u);
    }
    for (int i = tid; i < 320; i += 256) {             // halo scalars
        int side = i & 1;
        int rest = i >> 1;
        int pl   = rest / 10;
        int row  = rest - pl * 10;
        int ih = h0 - 1 + row;
        int iw = side ? (w0 + 64) : (w0 - 1);
        bool ok = ((unsigned)ih < 256u) && ((unsigned)iw < 256u);
        const float* src = xq + (size_t)pl * (HW_ * HW_) + (ok ? (ih * HW_ + iw) : 0);
        cp_async4(scr + (uint32_t)(pl * (10 * RAWP) + row * RAWP + (side ? 68 : 3)) * 4,
                  src, ok ? 4u : 0u);
    }
}

// convert scr f32 (16 planes) -> xsh packed f16x2 over adjacent planes
__device__ __forceinline__ void convert_half(const float* scr, uint32_t* xsh, int tid) {
    for (int i = tid; i < 2800; i += 256) {
        int j   = i / 350;
        int r1  = i - j * 350;
        int row = r1 / 35;
        int p2  = r1 - row * 35;
        const float* s0 = scr + (2 * j)     * (10 * RAWP) + row * RAWP + 2 * p2;
        const float* s1 = scr + (2 * j + 1) * (10 * RAWP) + row * RAWP + 2 * p2;
        float2 f0 = *(const float2*)s0;
        float2 f1 = *(const float2*)s1;
        uint2 o;
        o.x = pack_f16x2(f1.x, f0.x);
        o.y = pack_f16x2(f1.y, f0.y);
        *(uint2*)(xsh + j * (10 * XPH) + row * XPH + 2 * p2) = o;
    }
}

// compute one 16-ci half from xsh
__device__ __forceinline__ void compute_half(const uint32_t* xsh, const uint32_t* ws,
                                             float acc[2][2][4][4],
                                             int lane, int g, int tig, int wy, int wh) {
    const uint4* wf = (const uint4*)ws + lane;
    const uint32_t* xf = xsh + (2 * wy) * XPH + wh * 32 + g + 3 + tig * (10 * XPH);

#pragma unroll
    for (int kw = 0; kw < 3; kw++) {
        uint32_t B0[4][4], B1[4][4];
#pragma unroll
        for (int xr = 0; xr < 4; xr++) {
            const uint32_t* xt = xf + xr * XPH + kw;
#pragma unroll
            for (int nt = 0; nt < 4; nt++) {
                B0[xr][nt] = xt[nt * 8];
                B1[xr][nt] = xt[nt * 8 + 4 * (10 * XPH)];
            }
        }
#pragma unroll
        for (int kh = 0; kh < 3; kh++) {
            const int t = kh * 3 + kw;
            uint4 q0 = wf[(t * 2) * 32];
            uint4 q1 = wf[(t * 2 + 1) * 32];
            uint32_t a0[4] = {q0.x, q0.y, q0.z, q0.w};
            uint32_t a1[4] = {q1.x, q1.y, q1.z, q1.w};
#pragma unroll
            for (int r = 0; r < 2; r++) {
                const int xr = r + kh;
#pragma unroll
                for (int nt = 0; nt < 4; nt++) {
                    mma_f16(acc[r][0][nt], a0, B0[xr][nt], B1[xr][nt]);
                    mma_f16(acc[r][1][nt], a1, B0[xr][nt], B1[xr][nt]);
                }
            }
        }
    }
}

__device__ __forceinline__ void store_tile(float acc[2][2][4][4], float* __restrict__ out,
                                           const float* bs, int b, int oh0, int w0,
                                           int g, int tig, int wy, int wh) {
#pragma unroll
    for (int r = 0; r < 2; r++) {
        const int oh = oh0 + 2 * wy + r;
#pragma unroll
        for (int mt = 0; mt < 2; mt++) {
#pragma unroll
            for (int nt = 0; nt < 4; nt++) {
                int co = mt * 16 + g;
                int pw = w0 + wh * 32 + nt * 8 + 2 * tig;
                float2 v0, v1;
                v0.x = acc[r][mt][nt][0] + bs[co];
                v0.y = acc[r][mt][nt][1] + bs[co];
                v1.x = acc[r][mt][nt][2] + bs[co + 8];
                v1.y = acc[r][mt][nt][3] + bs[co + 8];
                *(float2*)&out[(((size_t)b * COUT_ + co)     * HW_ + oh) * HW_ + pw] = v0;
                *(float2*)&out[(((size_t)b * COUT_ + co + 8) * HW_ + oh) * HW_ + pw] = v1;
            }
        }
    }
}

// ---------------------------------------------------------------------------
// Kernel 2: conv. Grid (4, 16, 16); 256 threads, 8 warps; 2 h-tiles per CTA.
// jobs j=0..3: tile = j>>1 (h0 = hb + 8*tile), half = j&1 (ci = 16*half ..).
// ---------------------------------------------------------------------------
__global__ __launch_bounds__(256, 2)
void condconv_mma_kernel(const float* __restrict__ x, float* __restrict__ out) {
    extern __shared__ float sm[];
    const uint32_t sbase = smem_u32(sm);

    const int b  = blockIdx.z;
    const int hb = blockIdx.y * 16;      // base row of the 2-tile strip
    const int w0 = blockIdx.x * 64;
    const int tid = threadIdx.x;
    const int lane = tid & 31, wid = tid >> 5;
    const int g = lane >> 2, tig = lane & 3;
    const int wy = wid >> 1, wh = wid & 1;

    const uint32_t* gw = g_wt_h + b * 4608;
    const float* xb = x + (size_t)b * CIN_ * HW_ * HW_;
    uint32_t* xsh = (uint32_t*)(sm + XSH_U);
    const uint32_t* ws = (const uint32_t*)(sm + WS_U);
    const uint32_t scr_a = sbase + SCR_U * 4;

    if (tid < COUT_) sm[BIAS_U + tid] = g_bias[b * COUT_ + tid];

    // prologue: weights (both halves) + raw job0 in one cp.async group
    for (int i = tid; i < 1152; i += 256)
        cp_async16(sbase + (WS_U + i * 4) * 4, gw + i * 4);
    stage_raw(scr_a, xb, hb, w0, tid);
    CP_COMMIT();

    float acc[2][2][4][4];
#pragma unroll
    for (int r = 0; r < 2; r++)
#pragma unroll
        for (int mt = 0; mt < 2; mt++)
#pragma unroll
            for (int nt = 0; nt < 4; nt++)
#pragma unroll
                for (int i = 0; i < 4; i++) acc[r][mt][nt][i] = 0.f;

#pragma unroll 1
    for (int j = 0; j < 4; j++) {
        CP_WAIT0();
        __syncthreads();                 // raw(j) visible
        convert_half(sm + SCR_U, xsh, tid);
        __syncthreads();                 // xsh ready; scr free for reuse

        if (j < 3) {                     // prefetch raw(j+1) under compute(j)
            int nj = j + 1;
            stage_raw(scr_a, xb + (size_t)((nj & 1) * 16) * (HW_ * HW_),
                      hb + (nj >> 1) * 8, w0, tid);
            CP_COMMIT();
        }

        compute_half(xsh, ws + (j & 1) * 2304, acc, lane, g, tig, wy, wh);

        if (j == 1) {                    // tile 0 done
            store_tile(acc, out, sm + BIAS_U, b, hb, w0, g, tig, wy, wh);
#pragma unroll
            for (int r = 0; r < 2; r++)
#pragma unroll
                for (int mt = 0; mt < 2; mt++)
#pragma unroll
                    for (int nt = 0; nt < 4; nt++)
#pragma unroll
                        for (int i = 0; i < 4; i++) acc[r][mt][nt][i] = 0.f;
        }
    }

    store_tile(acc, out, sm + BIAS_U, b, hb + 8, w0, g, tig, wy, wh);
}

// ---------------------------------------------------------------------------
extern "C" void kernel_launch(void* const* d_in, const int* in_sizes, int n_in,
                              void* d_out, int out_size) {
    const float* x  = (const float*)d_in[0];
    const float* rw = (const float*)d_in[1];
    const float* ew = (const float*)d_in[2];
    const float* eb = (const float*)d_in[3];
    float* out = (float*)d_out;

    condconv_prep_kernel<<<dim3(B_, 2), 256>>>(rw, ew, eb);

    cudaFuncSetAttribute(condconv_mma_kernel,
                         cudaFuncAttributeMaxDynamicSharedMemorySize, SMEM_BYTES);
    dim3 grid(HW_ / 64, HW_ / 16, B_);
    condconv_mma_kernel<<<grid, 256, SMEM_BYTES>>>(x, out);
}